// round 2
// baseline (speedup 1.0000x reference)
#include <cuda_runtime.h>
#include <math.h>

// Problem constants
#define BATCH 64
#define NP 24
#define NPAT 576          // patches per image (24*24)
#define DH 768            // hidden dim
#define KDIM 768          // C*P*P = 3*16*16
#define LLAT 1024
#define HW 384
#define PSZ 16
#define TAU_INV 2.0f
#define EPSN 1e-8f
#define MTOT (BATCH*NPAT) // 36864

// Scratch (device globals: allocation-free rule)
__device__ float  g_A[MTOT * KDIM];   // im2col matrix, 113 MB
__device__ float  g_pn[MTOT * DH];    // patch embeddings -> normalized in place
__device__ float  g_ln[LLAT * DH];    // normalized latent
__device__ double g_far[BATCH];
__device__ double g_close[BATCH];

// ---------------------------------------------------------------- init
__global__ void init_k() {
    int t = threadIdx.x;
    if (t < BATCH) { g_far[t] = 0.0; g_close[t] = 0.0; }
}

// ---------------------------------------------------------------- im2col
// g_A[row][k], row = b*576 + ph*24 + pw, k = c*256 + kh*16 + kw
// vectorized float4 over k (kw runs of 16 are contiguous in x)
__global__ void im2col_k(const float* __restrict__ x) {
    int idx = blockIdx.x * 256 + threadIdx.x;         // over MTOT*KDIM/4
    int kq  = idx % (KDIM / 4);
    int row = idx / (KDIM / 4);
    int k  = kq * 4;
    int kw = k & 15, kh = (k >> 4) & 15, c = k >> 8;
    int pw = row % NP; int t = row / NP; int ph = t % NP; int b = t / NP;
    const float4* src = (const float4*)(x + ((size_t)(b*3 + c)*HW + ph*PSZ + kh)*HW + pw*PSZ + kw);
    ((float4*)g_A)[idx] = *src;
}

// ---------------------------------------------------------------- GEMM1: patch embed
// g_pn[row][d] = sum_k g_A[row][k] * W[d][k] + bias[d]
// 64x64 tile, BK=16, 16x16 threads, 4x4 per thread (NT, both K-contiguous)
__global__ void gemm_embed_k(const float* __restrict__ W, const float* __restrict__ bias) {
    __shared__ float As[16][64];
    __shared__ float Bs[16][64];
    int tx = threadIdx.x, ty = threadIdx.y;
    int tid = ty * 16 + tx;
    const float* aBase = g_A + (size_t)blockIdx.x * 64 * KDIM;
    const float* bBase = W   + (size_t)blockIdx.y * 64 * KDIM;
    int lr = tid >> 2;          // 0..63 tile row
    int lk = (tid & 3) * 4;     // 0,4,8,12
    float acc[4][4] = {};
    for (int k0 = 0; k0 < KDIM; k0 += 16) {
        float4 av = *(const float4*)(aBase + (size_t)lr * KDIM + k0 + lk);
        float4 bv = *(const float4*)(bBase + (size_t)lr * KDIM + k0 + lk);
        __syncthreads();
        As[lk+0][lr] = av.x; As[lk+1][lr] = av.y; As[lk+2][lr] = av.z; As[lk+3][lr] = av.w;
        Bs[lk+0][lr] = bv.x; Bs[lk+1][lr] = bv.y; Bs[lk+2][lr] = bv.z; Bs[lk+3][lr] = bv.w;
        __syncthreads();
        #pragma unroll
        for (int kk = 0; kk < 16; kk++) {
            float4 a = *(const float4*)&As[kk][ty*4];
            float4 b = *(const float4*)&Bs[kk][tx*4];
            float ar[4] = {a.x,a.y,a.z,a.w}, br[4] = {b.x,b.y,b.z,b.w};
            #pragma unroll
            for (int i = 0; i < 4; i++)
                #pragma unroll
                for (int j = 0; j < 4; j++) acc[i][j] += ar[i] * br[j];
        }
    }
    int row = blockIdx.x * 64 + ty * 4;
    int col = blockIdx.y * 64 + tx * 4;
    #pragma unroll
    for (int i = 0; i < 4; i++)
        #pragma unroll
        for (int j = 0; j < 4; j++)
            g_pn[(size_t)(row + i) * DH + col + j] = acc[i][j] + bias[col + j];
}

// ---------------------------------------------------------------- L2 normalize (warp per row)
__global__ void norm_patch_k() {
    int gw = (blockIdx.x * blockDim.x + threadIdx.x) >> 5;
    int lane = threadIdx.x & 31;
    if (gw >= MTOT) return;
    float4* r = (float4*)(g_pn + (size_t)gw * DH);
    float s = 0.f; float4 v[6];
    #pragma unroll
    for (int i = 0; i < 6; i++) {
        v[i] = r[lane + 32*i];
        s += v[i].x*v[i].x + v[i].y*v[i].y + v[i].z*v[i].z + v[i].w*v[i].w;
    }
    #pragma unroll
    for (int o = 16; o; o >>= 1) s += __shfl_xor_sync(0xffffffffu, s, o);
    float inv = 1.0f / fmaxf(sqrtf(s), EPSN);
    #pragma unroll
    for (int i = 0; i < 6; i++) {
        v[i].x *= inv; v[i].y *= inv; v[i].z *= inv; v[i].w *= inv;
        r[lane + 32*i] = v[i];
    }
}

__global__ void norm_latent_k(const float* __restrict__ latent) {
    int gw = (blockIdx.x * blockDim.x + threadIdx.x) >> 5;
    int lane = threadIdx.x & 31;
    if (gw >= LLAT) return;
    const float4* src = (const float4*)(latent + (size_t)gw * DH);
    float4* dst = (float4*)(g_ln + (size_t)gw * DH);
    float s = 0.f; float4 v[6];
    #pragma unroll
    for (int i = 0; i < 6; i++) {
        v[i] = src[lane + 32*i];
        s += v[i].x*v[i].x + v[i].y*v[i].y + v[i].z*v[i].z + v[i].w*v[i].w;
    }
    #pragma unroll
    for (int o = 16; o; o >>= 1) s += __shfl_xor_sync(0xffffffffu, s, o);
    float inv = 1.0f / fmaxf(sqrtf(s), EPSN);
    #pragma unroll
    for (int i = 0; i < 6; i++) {
        v[i].x *= inv; v[i].y *= inv; v[i].z *= inv; v[i].w *= inv;
        dst[lane + 32*i] = v[i];
    }
}

// ---------------------------------------------------------------- far: sum exp(pn.pn^T / tau) off-diag
// symmetric: compute upper-triangle tiles, weight off-diag tiles by 2
__global__ void far_k() {
    int ti = blockIdx.x, tj = blockIdx.y, b = blockIdx.z;
    if (tj < ti) return;
    __shared__ float As[16][64];
    __shared__ float Bs[16][64];
    __shared__ float red[256];
    int tx = threadIdx.x, ty = threadIdx.y;
    int tid = ty * 16 + tx;
    const float* aBase = g_pn + ((size_t)b * NPAT + ti * 64) * DH;
    const float* bBase = g_pn + ((size_t)b * NPAT + tj * 64) * DH;
    int lr = tid >> 2;
    int lk = (tid & 3) * 4;
    float acc[4][4] = {};
    for (int k0 = 0; k0 < DH; k0 += 16) {
        float4 av = *(const float4*)(aBase + (size_t)lr * DH + k0 + lk);
        float4 bv = *(const float4*)(bBase + (size_t)lr * DH + k0 + lk);
        __syncthreads();
        As[lk+0][lr] = av.x; As[lk+1][lr] = av.y; As[lk+2][lr] = av.z; As[lk+3][lr] = av.w;
        Bs[lk+0][lr] = bv.x; Bs[lk+1][lr] = bv.y; Bs[lk+2][lr] = bv.z; Bs[lk+3][lr] = bv.w;
        __syncthreads();
        #pragma unroll
        for (int kk = 0; kk < 16; kk++) {
            float4 a = *(const float4*)&As[kk][ty*4];
            float4 b2 = *(const float4*)&Bs[kk][tx*4];
            float ar[4] = {a.x,a.y,a.z,a.w}, br[4] = {b2.x,b2.y,b2.z,b2.w};
            #pragma unroll
            for (int i = 0; i < 4; i++)
                #pragma unroll
                for (int j = 0; j < 4; j++) acc[i][j] += ar[i] * br[j];
        }
    }
    float part = 0.f;
    bool diag = (ti == tj);
    #pragma unroll
    for (int i = 0; i < 4; i++) {
        #pragma unroll
        for (int j = 0; j < 4; j++) {
            float e = __expf(acc[i][j] * TAU_INV);
            if (diag) {
                int gr = ti * 64 + ty * 4 + i, gc = tj * 64 + tx * 4 + j;
                if (gr != gc) part += e;
            } else {
                part += 2.0f * e;
            }
        }
    }
    red[tid] = part; __syncthreads();
    for (int s = 128; s > 0; s >>= 1) {
        if (tid < s) red[tid] += red[tid + s];
        __syncthreads();
    }
    if (tid == 0) atomicAdd(&g_far[b], (double)red[0]);
}

// ---------------------------------------------------------------- close: sum exp(pn.ln^T / tau)
__global__ void close_k() {
    int ti = blockIdx.x, tj = blockIdx.y, b = blockIdx.z;
    __shared__ float As[16][64];
    __shared__ float Bs[16][64];
    __shared__ float red[256];
    int tx = threadIdx.x, ty = threadIdx.y;
    int tid = ty * 16 + tx;
    const float* aBase = g_pn + ((size_t)b * NPAT + ti * 64) * DH;
    const float* bBase = g_ln + (size_t)tj * 64 * DH;
    int lr = tid >> 2;
    int lk = (tid & 3) * 4;
    float acc[4][4] = {};
    for (int k0 = 0; k0 < DH; k0 += 16) {
        float4 av = *(const float4*)(aBase + (size_t)lr * DH + k0 + lk);
        float4 bv = *(const float4*)(bBase + (size_t)lr * DH + k0 + lk);
        __syncthreads();
        As[lk+0][lr] = av.x; As[lk+1][lr] = av.y; As[lk+2][lr] = av.z; As[lk+3][lr] = av.w;
        Bs[lk+0][lr] = bv.x; Bs[lk+1][lr] = bv.y; Bs[lk+2][lr] = bv.z; Bs[lk+3][lr] = bv.w;
        __syncthreads();
        #pragma unroll
        for (int kk = 0; kk < 16; kk++) {
            float4 a = *(const float4*)&As[kk][ty*4];
            float4 b2 = *(const float4*)&Bs[kk][tx*4];
            float ar[4] = {a.x,a.y,a.z,a.w}, br[4] = {b2.x,b2.y,b2.z,b2.w};
            #pragma unroll
            for (int i = 0; i < 4; i++)
                #pragma unroll
                for (int j = 0; j < 4; j++) acc[i][j] += ar[i] * br[j];
        }
    }
    float part = 0.f;
    #pragma unroll
    for (int i = 0; i < 4; i++)
        #pragma unroll
        for (int j = 0; j < 4; j++)
            part += __expf(acc[i][j] * TAU_INV);
    red[tid] = part; __syncthreads();
    for (int s = 128; s > 0; s >>= 1) {
        if (tid < s) red[tid] += red[tid + s];
        __syncthreads();
    }
    if (tid == 0) atomicAdd(&g_close[b], (double)red[0]);
}

// ---------------------------------------------------------------- finish: mean(-log(close/far))
__global__ void finish_k(float* out) {
    __shared__ double sh[BATCH];
    int t = threadIdx.x;
    sh[t] = log(g_far[t]) - log(g_close[t]);
    __syncthreads();
    if (t == 0) {
        double s = 0.0;
        for (int i = 0; i < BATCH; i++) s += sh[i];
        out[0] = (float)(s / (double)BATCH);
    }
}

// ---------------------------------------------------------------- launch
extern "C" void kernel_launch(void* const* d_in, const int* in_sizes, int n_in,
                              void* d_out, int out_size) {
    const float* x      = (const float*)d_in[0];
    const float* conv_w = (const float*)d_in[1];
    const float* conv_b = (const float*)d_in[2];
    const float* latent = (const float*)d_in[3];
    float* out = (float*)d_out;

    init_k<<<1, 64>>>();
    im2col_k<<<(MTOT * KDIM / 4) / 256, 256>>>(x);
    gemm_embed_k<<<dim3(MTOT / 64, DH / 64), dim3(16, 16)>>>(conv_w, conv_b);
    norm_patch_k<<<(MTOT * 32) / 256, 256>>>();
    norm_latent_k<<<(LLAT * 32) / 256, 256>>>(latent);
    far_k<<<dim3(NPAT / 64, NPAT / 64, BATCH), dim3(16, 16)>>>();
    close_k<<<dim3(NPAT / 64, LLAT / 64, BATCH), dim3(16, 16)>>>();
    finish_k<<<1, BATCH>>>(out);
}

// round 5
// speedup vs baseline: 4.7772x; 4.7772x over previous
#include <cuda_runtime.h>
#include <cuda_bf16.h>
#include <math.h>
#include <stdint.h>

// Problem constants
#define BATCH 64
#define NP 24
#define NPAT 576
#define DH 768
#define KDIM 768
#define LLAT 1024
#define HW 384
#define PSZ 16
#define TAU_INV 2.0f
#define EPSN 1e-8f
#define MTOT (BATCH*NPAT) // 36864

// Scratch
__device__ __nv_bfloat16 g_Ah[(size_t)MTOT * KDIM];  // im2col bf16, 56.6 MB
__device__ __nv_bfloat16 g_Wh[(size_t)DH * KDIM];    // conv weight bf16
__device__ float         g_pn[(size_t)MTOT * DH];    // embeddings fp32
__device__ __nv_bfloat16 g_pnh[(size_t)MTOT * DH];   // normalized bf16
__device__ __nv_bfloat16 g_lnh[(size_t)LLAT * DH];   // normalized latent bf16
__device__ double g_far[BATCH];
__device__ double g_close[BATCH];

#define BKP 40   // padded smem row (bf16 elems): 80B stride, conflict-free frag loads

// ---------------------------------------------------------------- mma primitive
__device__ __forceinline__ void mma16816(float c[4],
    uint32_t a0, uint32_t a1, uint32_t a2, uint32_t a3,
    uint32_t b0, uint32_t b1)
{
    asm volatile(
        "mma.sync.aligned.m16n8k16.row.col.f32.bf16.bf16.f32 "
        "{%0,%1,%2,%3}, {%4,%5,%6,%7}, {%8,%9}, {%0,%1,%2,%3};\n"
        : "+f"(c[0]), "+f"(c[1]), "+f"(c[2]), "+f"(c[3])
        : "r"(a0), "r"(a1), "r"(a2), "r"(a3), "r"(b0), "r"(b1));
}

// load 64 rows x 32 k bf16 from global (row stride ldk) into smem [64][BKP]
__device__ __forceinline__ void load_tile(__nv_bfloat16* s,
                                          const __nv_bfloat16* gsrc,
                                          int ldk, int tid)
{
    #pragma unroll
    for (int it = 0; it < 2; it++) {
        int r  = (tid >> 2) + it * 32;
        int ch = (tid & 3) * 8;
        *(int4*)(s + r * BKP + ch) = *(const int4*)(gsrc + (size_t)r * ldk + ch);
    }
}

// core: accumulate 32x32 warp tile over one BK=32 chunk already in smem
__device__ __forceinline__ void mma_chunk(const __nv_bfloat16* As,
                                          const __nv_bfloat16* Bs,
                                          int wr, int wc, int g, int ti,
                                          float acc[2][4][4])
{
    #pragma unroll
    for (int ks = 0; ks < 2; ks++) {
        int ko = ks * 16 + ti * 2;
        uint32_t a[2][4], b[4][2];
        #pragma unroll
        for (int mi = 0; mi < 2; mi++) {
            const __nv_bfloat16* base = As + (wr + mi * 16 + g) * BKP + ko;
            a[mi][0] = *(const uint32_t*)(base);
            a[mi][1] = *(const uint32_t*)(base + 8 * BKP);
            a[mi][2] = *(const uint32_t*)(base + 8);
            a[mi][3] = *(const uint32_t*)(base + 8 * BKP + 8);
        }
        #pragma unroll
        for (int nj = 0; nj < 4; nj++) {
            const __nv_bfloat16* base = Bs + (wc + nj * 8 + g) * BKP + ko;
            b[nj][0] = *(const uint32_t*)(base);
            b[nj][1] = *(const uint32_t*)(base + 8);
        }
        #pragma unroll
        for (int mi = 0; mi < 2; mi++)
            #pragma unroll
            for (int nj = 0; nj < 4; nj++)
                mma16816(acc[mi][nj], a[mi][0], a[mi][1], a[mi][2], a[mi][3],
                         b[nj][0], b[nj][1]);
    }
}

// ---------------------------------------------------------------- init
__global__ void init_k() {
    int t = threadIdx.x;
    if (t < BATCH) { g_far[t] = 0.0; g_close[t] = 0.0; }
}

// ---------------------------------------------------------------- im2col -> bf16
__global__ void im2col_k(const float* __restrict__ x) {
    int idx = blockIdx.x * 256 + threadIdx.x;         // over MTOT*KDIM/8
    int kq  = idx % (KDIM / 8);
    int row = idx / (KDIM / 8);
    int k  = kq * 8;
    int kw = k & 15, kh = (k >> 4) & 15, c = k >> 8;
    int pw = row % NP; int t = row / NP; int ph = t % NP; int b = t / NP;
    const float* src = x + ((size_t)(b*3 + c)*HW + ph*PSZ + kh)*HW + pw*PSZ + kw;
    float4 v0 = *(const float4*)(src);
    float4 v1 = *(const float4*)(src + 4);
    __nv_bfloat16 o[8];
    o[0]=__float2bfloat16_rn(v0.x); o[1]=__float2bfloat16_rn(v0.y);
    o[2]=__float2bfloat16_rn(v0.z); o[3]=__float2bfloat16_rn(v0.w);
    o[4]=__float2bfloat16_rn(v1.x); o[5]=__float2bfloat16_rn(v1.y);
    o[6]=__float2bfloat16_rn(v1.z); o[7]=__float2bfloat16_rn(v1.w);
    *(int4*)(g_Ah + (size_t)row * KDIM + k) = *(int4*)o;
}

// ---------------------------------------------------------------- W -> bf16
__global__ void wconv_k(const float* __restrict__ W) {
    int idx = blockIdx.x * 256 + threadIdx.x;  // over DH*KDIM/8
    const float4* src = (const float4*)(W + (size_t)idx * 8);
    float4 v0 = src[0], v1 = src[1];
    __nv_bfloat16 o[8];
    o[0]=__float2bfloat16_rn(v0.x); o[1]=__float2bfloat16_rn(v0.y);
    o[2]=__float2bfloat16_rn(v0.z); o[3]=__float2bfloat16_rn(v0.w);
    o[4]=__float2bfloat16_rn(v1.x); o[5]=__float2bfloat16_rn(v1.y);
    o[6]=__float2bfloat16_rn(v1.z); o[7]=__float2bfloat16_rn(v1.w);
    *(int4*)(g_Wh + (size_t)idx * 8) = *(int4*)o;
}

// ---------------------------------------------------------------- GEMM embed (tensor)
__global__ void gemm_embed_k(const float* __restrict__ bias) {
    __shared__ __align__(16) __nv_bfloat16 As[64 * BKP];
    __shared__ __align__(16) __nv_bfloat16 Bs[64 * BKP];
    int tid = threadIdx.x;
    int lane = tid & 31, warp = tid >> 5;
    int wr = (warp >> 1) * 32, wc = (warp & 1) * 32;
    int g = lane >> 2, ti = lane & 3;
    const __nv_bfloat16* aBase = g_Ah + (size_t)blockIdx.x * 64 * KDIM;
    const __nv_bfloat16* bBase = g_Wh + (size_t)blockIdx.y * 64 * KDIM;
    float acc[2][4][4] = {};
    for (int k0 = 0; k0 < KDIM; k0 += 32) {
        __syncthreads();
        load_tile(As, aBase + k0, KDIM, tid);
        load_tile(Bs, bBase + k0, KDIM, tid);
        __syncthreads();
        mma_chunk(As, Bs, wr, wc, g, ti, acc);
    }
    int rowB = blockIdx.x * 64 + wr;
    int colB = blockIdx.y * 64 + wc;
    #pragma unroll
    for (int mi = 0; mi < 2; mi++)
        #pragma unroll
        for (int nj = 0; nj < 4; nj++) {
            int col = colB + nj * 8 + ti * 2;
            float b0 = bias[col], b1 = bias[col + 1];
            int r0 = rowB + mi * 16 + g;
            float2 v0 = { acc[mi][nj][0] + b0, acc[mi][nj][1] + b1 };
            float2 v1 = { acc[mi][nj][2] + b0, acc[mi][nj][3] + b1 };
            *(float2*)(g_pn + (size_t)r0 * DH + col)       = v0;
            *(float2*)(g_pn + (size_t)(r0 + 8) * DH + col) = v1;
        }
}

// ---------------------------------------------------------------- L2 normalize patches fp32 -> bf16
__global__ void norm_patch_k() {
    int gw = (blockIdx.x * blockDim.x + threadIdx.x) >> 5;
    int lane = threadIdx.x & 31;
    if (gw >= MTOT) return;
    const float4* r = (const float4*)(g_pn + (size_t)gw * DH);
    ushort4* dst = (ushort4*)(g_pnh + (size_t)gw * DH);
    float s = 0.f; float4 v[6];
    #pragma unroll
    for (int i = 0; i < 6; i++) {
        v[i] = r[lane + 32*i];
        s += v[i].x*v[i].x + v[i].y*v[i].y + v[i].z*v[i].z + v[i].w*v[i].w;
    }
    #pragma unroll
    for (int o = 16; o; o >>= 1) s += __shfl_xor_sync(0xffffffffu, s, o);
    float inv = 1.0f / fmaxf(sqrtf(s), EPSN);
    #pragma unroll
    for (int i = 0; i < 6; i++) {
        __nv_bfloat16 o4[4];
        o4[0] = __float2bfloat16_rn(v[i].x * inv);
        o4[1] = __float2bfloat16_rn(v[i].y * inv);
        o4[2] = __float2bfloat16_rn(v[i].z * inv);
        o4[3] = __float2bfloat16_rn(v[i].w * inv);
        dst[lane + 32*i] = *(ushort4*)o4;
    }
}

__global__ void norm_latent_k(const float* __restrict__ latent) {
    int gw = (blockIdx.x * blockDim.x + threadIdx.x) >> 5;
    int lane = threadIdx.x & 31;
    if (gw >= LLAT) return;
    const float4* src = (const float4*)(latent + (size_t)gw * DH);
    ushort4* dst = (ushort4*)(g_lnh + (size_t)gw * DH);
    float s = 0.f; float4 v[6];
    #pragma unroll
    for (int i = 0; i < 6; i++) {
        v[i] = src[lane + 32*i];
        s += v[i].x*v[i].x + v[i].y*v[i].y + v[i].z*v[i].z + v[i].w*v[i].w;
    }
    #pragma unroll
    for (int o = 16; o; o >>= 1) s += __shfl_xor_sync(0xffffffffu, s, o);
    float inv = 1.0f / fmaxf(sqrtf(s), EPSN);
    #pragma unroll
    for (int i = 0; i < 6; i++) {
        __nv_bfloat16 o4[4];
        o4[0] = __float2bfloat16_rn(v[i].x * inv);
        o4[1] = __float2bfloat16_rn(v[i].y * inv);
        o4[2] = __float2bfloat16_rn(v[i].z * inv);
        o4[3] = __float2bfloat16_rn(v[i].w * inv);
        dst[lane + 32*i] = *(ushort4*)o4;
    }
}

// ---------------------------------------------------------------- far (tensor, upper triangle)
__global__ void far_k() {
    int tib = blockIdx.x, tjb = blockIdx.y, b = blockIdx.z;
    if (tjb < tib) return;
    __shared__ __align__(16) __nv_bfloat16 As[64 * BKP];
    __shared__ __align__(16) __nv_bfloat16 Bs[64 * BKP];
    __shared__ float red[128];
    int tid = threadIdx.x;
    int lane = tid & 31, warp = tid >> 5;
    int wr = (warp >> 1) * 32, wc = (warp & 1) * 32;
    int g = lane >> 2, ti = lane & 3;
    const __nv_bfloat16* aBase = g_pnh + ((size_t)b * NPAT + tib * 64) * DH;
    const __nv_bfloat16* bBase = g_pnh + ((size_t)b * NPAT + tjb * 64) * DH;
    float acc[2][4][4] = {};
    for (int k0 = 0; k0 < DH; k0 += 32) {
        __syncthreads();
        load_tile(As, aBase + k0, DH, tid);
        load_tile(Bs, bBase + k0, DH, tid);
        __syncthreads();
        mma_chunk(As, Bs, wr, wc, g, ti, acc);
    }
    float part = 0.f;
    bool diag = (tib == tjb);
    #pragma unroll
    for (int mi = 0; mi < 2; mi++)
        #pragma unroll
        for (int nj = 0; nj < 4; nj++) {
            int gr0 = tib * 64 + wr + mi * 16 + g;
            int gc0 = tjb * 64 + wc + nj * 8 + ti * 2;
            float e0 = __expf(acc[mi][nj][0] * TAU_INV);
            float e1 = __expf(acc[mi][nj][1] * TAU_INV);
            float e2 = __expf(acc[mi][nj][2] * TAU_INV);
            float e3 = __expf(acc[mi][nj][3] * TAU_INV);
            if (diag) {
                part += (gr0     != gc0    ) ? e0 : 0.f;
                part += (gr0     != gc0 + 1) ? e1 : 0.f;
                part += (gr0 + 8 != gc0    ) ? e2 : 0.f;
                part += (gr0 + 8 != gc0 + 1) ? e3 : 0.f;
            } else {
                part += 2.0f * (e0 + e1 + e2 + e3);
            }
        }
    red[tid] = part; __syncthreads();
    for (int s = 64; s > 0; s >>= 1) {
        if (tid < s) red[tid] += red[tid + s];
        __syncthreads();
    }
    if (tid == 0) atomicAdd(&g_far[b], (double)red[0]);
}

// ---------------------------------------------------------------- close (tensor)
__global__ void close_k() {
    int tib = blockIdx.x, tjb = blockIdx.y, b = blockIdx.z;
    __shared__ __align__(16) __nv_bfloat16 As[64 * BKP];
    __shared__ __align__(16) __nv_bfloat16 Bs[64 * BKP];
    __shared__ float red[128];
    int tid = threadIdx.x;
    int lane = tid & 31, warp = tid >> 5;
    int wr = (warp >> 1) * 32, wc = (warp & 1) * 32;
    int g = lane >> 2, ti = lane & 3;
    const __nv_bfloat16* aBase = g_pnh + ((size_t)b * NPAT + tib * 64) * DH;
    const __nv_bfloat16* bBase = g_lnh + (size_t)tjb * 64 * DH;
    float acc[2][4][4] = {};
    for (int k0 = 0; k0 < DH; k0 += 32) {
        __syncthreads();
        load_tile(As, aBase + k0, DH, tid);
        load_tile(Bs, bBase + k0, DH, tid);
        __syncthreads();
        mma_chunk(As, Bs, wr, wc, g, ti, acc);
    }
    float part = 0.f;
    #pragma unroll
    for (int mi = 0; mi < 2; mi++)
        #pragma unroll
        for (int nj = 0; nj < 4; nj++) {
            part += __expf(acc[mi][nj][0] * TAU_INV);
            part += __expf(acc[mi][nj][1] * TAU_INV);
            part += __expf(acc[mi][nj][2] * TAU_INV);
            part += __expf(acc[mi][nj][3] * TAU_INV);
        }
    red[tid] = part; __syncthreads();
    for (int s = 64; s > 0; s >>= 1) {
        if (tid < s) red[tid] += red[tid + s];
        __syncthreads();
    }
    if (tid == 0) atomicAdd(&g_close[b], (double)red[0]);
}

// ---------------------------------------------------------------- finish
__global__ void finish_k(float* out) {
    __shared__ double sh[BATCH];
    int t = threadIdx.x;
    sh[t] = log(g_far[t]) - log(g_close[t]);
    __syncthreads();
    if (t == 0) {
        double s = 0.0;
        for (int i = 0; i < BATCH; i++) s += sh[i];
        out[0] = (float)(s / (double)BATCH);
    }
}

// ---------------------------------------------------------------- launch
extern "C" void kernel_launch(void* const* d_in, const int* in_sizes, int n_in,
                              void* d_out, int out_size) {
    const float* x      = (const float*)d_in[0];
    const float* conv_w = (const float*)d_in[1];
    const float* conv_b = (const float*)d_in[2];
    const float* latent = (const float*)d_in[3];
    float* out = (float*)d_out;

    init_k<<<1, 64>>>();
    im2col_k<<<(MTOT * (KDIM / 8)) / 256, 256>>>(x);
    wconv_k<<<(DH * KDIM / 8) / 256, 256>>>(conv_w);
    gemm_embed_k<<<dim3(MTOT / 64, DH / 64), 128>>>(conv_b);
    norm_patch_k<<<(MTOT * 32) / 256, 256>>>();
    norm_latent_k<<<(LLAT * 32) / 256, 256>>>(latent);
    far_k<<<dim3(NPAT / 64, NPAT / 64, BATCH), 128>>>();
    close_k<<<dim3(NPAT / 64, LLAT / 64, BATCH), 128>>>();
    finish_k<<<1, BATCH>>>(out);
}

// round 6
// speedup vs baseline: 7.4689x; 1.5634x over previous
#include <cuda_runtime.h>
#include <cuda_bf16.h>
#include <math.h>
#include <stdint.h>

// Problem constants
#define BATCH 64
#define NP 24
#define NPAT 576
#define DH 768
#define KDIM 768
#define LLAT 1024
#define HW 384
#define PSZ 16
#define TAU_INV 2.0f
#define EPSN 1e-8f
#define MTOT (BATCH*NPAT) // 36864

// GEMM tiling
#define BM 128
#define BN 128
#define BKC 32
#define BKP 40           // padded smem row stride (bf16): conflict-free LDSM
#define NTHR 256

// Scratch
__device__ __nv_bfloat16 g_Ah[(size_t)MTOT * KDIM];        // im2col bf16
__device__ __nv_bfloat16 g_Wh[(size_t)DH * KDIM];          // conv weight bf16
__device__ float         g_pn[(size_t)MTOT * DH];          // embeddings fp32
__device__ __nv_bfloat16 g_pnh[(size_t)(MTOT + 128) * DH]; // normalized bf16 (+pad rows)
__device__ __nv_bfloat16 g_lnh[(size_t)LLAT * DH];         // normalized latent bf16
__device__ double g_far[BATCH];
__device__ double g_close[BATCH];

// ---------------------------------------------------------------- PTX helpers
__device__ __forceinline__ void mma16816(float c[4],
    uint32_t a0, uint32_t a1, uint32_t a2, uint32_t a3,
    uint32_t b0, uint32_t b1)
{
    asm volatile(
        "mma.sync.aligned.m16n8k16.row.col.f32.bf16.bf16.f32 "
        "{%0,%1,%2,%3}, {%4,%5,%6,%7}, {%8,%9}, {%0,%1,%2,%3};\n"
        : "+f"(c[0]), "+f"(c[1]), "+f"(c[2]), "+f"(c[3])
        : "r"(a0), "r"(a1), "r"(a2), "r"(a3), "r"(b0), "r"(b1));
}

__device__ __forceinline__ void cpa16(uint32_t dst, const void* src) {
    asm volatile("cp.async.cg.shared.global [%0], [%1], 16;\n" :: "r"(dst), "l"(src));
}
__device__ __forceinline__ void cp_commit() { asm volatile("cp.async.commit_group;\n"); }
__device__ __forceinline__ void cp_wait0()  { asm volatile("cp.async.wait_group 0;\n"); }

__device__ __forceinline__ void ldsm4(uint32_t& r0, uint32_t& r1, uint32_t& r2, uint32_t& r3,
                                      uint32_t addr)
{
    asm volatile("ldmatrix.sync.aligned.m8n8.x4.shared.b16 {%0,%1,%2,%3}, [%4];\n"
                 : "=r"(r0), "=r"(r1), "=r"(r2), "=r"(r3) : "r"(addr));
}

// ---------------------------------------------------------------- tile loader (cp.async)
// 128 rows x 32 k bf16 from global (row stride ldk) into smem stage
__device__ __forceinline__ void load_stage(uint32_t sAu, uint32_t sBu,
    const __nv_bfloat16* aG, int ldA,
    const __nv_bfloat16* bG, int ldB, int k0, int tid)
{
    #pragma unroll
    for (int it = 0; it < 2; it++) {
        int idx = tid + it * NTHR;
        int row = idx >> 2;
        int ch  = (idx & 3) * 8;
        cpa16(sAu + (uint32_t)(row * BKP + ch) * 2, aG + (size_t)row * ldA + k0 + ch);
        cpa16(sBu + (uint32_t)(row * BKP + ch) * 2, bG + (size_t)row * ldB + k0 + ch);
    }
}

// ---------------------------------------------------------------- shared mainloop
// 128x128 block tile, 8 warps of 64x32, BK=32 double-buffered cp.async
__device__ __forceinline__ void mainloop(
    const __nv_bfloat16* __restrict__ aG, int ldA,
    const __nv_bfloat16* __restrict__ bG, int ldB,
    int nk, uint32_t sAu, uint32_t sBu, float acc[4][4][4])
{
    int tid  = threadIdx.x;
    int lane = tid & 31, warp = tid >> 5;
    int wm = (warp >> 2) * 64;   // 0,64
    int wn = (warp & 3) * 32;    // 0,32,64,96
    int arow  = lane & 15;
    int acol8 = (lane >> 4) * 8;
    int bn  = ((lane >> 4) & 1) * 8 + (lane & 7);
    int bk8 = ((lane >> 3) & 1) * 8;
    const uint32_t stg = (uint32_t)BM * BKP * 2;  // bytes per tile stage

    uint32_t aAddr[4], bAddr[2];
    #pragma unroll
    for (int mi = 0; mi < 4; mi++)
        aAddr[mi] = sAu + (uint32_t)((wm + mi * 16 + arow) * BKP + acol8) * 2;
    #pragma unroll
    for (int p = 0; p < 2; p++)
        bAddr[p] = sBu + (uint32_t)((wn + p * 16 + bn) * BKP + bk8) * 2;

    load_stage(sAu, sBu, aG, ldA, bG, ldB, 0, tid);
    cp_commit();

    int buf = 0;
    for (int kc = 0; kc < nk; kc++) {
        cp_wait0();
        __syncthreads();
        if (kc + 1 < nk) {
            load_stage(sAu + (uint32_t)(buf ^ 1) * stg, sBu + (uint32_t)(buf ^ 1) * stg,
                       aG, ldA, bG, ldB, (kc + 1) * BKC, tid);
            cp_commit();
        }
        uint32_t off = (uint32_t)buf * stg;
        #pragma unroll
        for (int ks = 0; ks < 2; ks++) {
            uint32_t ko2 = (uint32_t)(ks * 16) * 2;
            uint32_t a[4][4], b[4][2];
            #pragma unroll
            for (int mi = 0; mi < 4; mi++)
                ldsm4(a[mi][0], a[mi][1], a[mi][2], a[mi][3], aAddr[mi] + off + ko2);
            #pragma unroll
            for (int p = 0; p < 2; p++)
                ldsm4(b[p*2][0], b[p*2][1], b[p*2+1][0], b[p*2+1][1], bAddr[p] + off + ko2);
            #pragma unroll
            for (int mi = 0; mi < 4; mi++)
                #pragma unroll
                for (int nj = 0; nj < 4; nj++)
                    mma16816(acc[mi][nj], a[mi][0], a[mi][1], a[mi][2], a[mi][3],
                             b[nj][0], b[nj][1]);
        }
        buf ^= 1;
    }
}

// ---------------------------------------------------------------- init
__global__ void init_k() {
    int t = threadIdx.x;
    if (t < BATCH) { g_far[t] = 0.0; g_close[t] = 0.0; }
}

// ---------------------------------------------------------------- im2col -> bf16
__global__ void im2col_k(const float* __restrict__ x) {
    int idx = blockIdx.x * 256 + threadIdx.x;
    int kq  = idx % (KDIM / 8);
    int row = idx / (KDIM / 8);
    int k  = kq * 8;
    int kw = k & 15, kh = (k >> 4) & 15, c = k >> 8;
    int pw = row % NP; int t = row / NP; int ph = t % NP; int b = t / NP;
    const float* src = x + ((size_t)(b*3 + c)*HW + ph*PSZ + kh)*HW + pw*PSZ + kw;
    float4 v0 = *(const float4*)(src);
    float4 v1 = *(const float4*)(src + 4);
    __nv_bfloat16 o[8];
    o[0]=__float2bfloat16_rn(v0.x); o[1]=__float2bfloat16_rn(v0.y);
    o[2]=__float2bfloat16_rn(v0.z); o[3]=__float2bfloat16_rn(v0.w);
    o[4]=__float2bfloat16_rn(v1.x); o[5]=__float2bfloat16_rn(v1.y);
    o[6]=__float2bfloat16_rn(v1.z); o[7]=__float2bfloat16_rn(v1.w);
    *(int4*)(g_Ah + (size_t)row * KDIM + k) = *(int4*)o;
}

// ---------------------------------------------------------------- W -> bf16
__global__ void wconv_k(const float* __restrict__ W) {
    int idx = blockIdx.x * 256 + threadIdx.x;
    const float4* src = (const float4*)(W + (size_t)idx * 8);
    float4 v0 = src[0], v1 = src[1];
    __nv_bfloat16 o[8];
    o[0]=__float2bfloat16_rn(v0.x); o[1]=__float2bfloat16_rn(v0.y);
    o[2]=__float2bfloat16_rn(v0.z); o[3]=__float2bfloat16_rn(v0.w);
    o[4]=__float2bfloat16_rn(v1.x); o[5]=__float2bfloat16_rn(v1.y);
    o[6]=__float2bfloat16_rn(v1.z); o[7]=__float2bfloat16_rn(v1.w);
    *(int4*)(g_Wh + (size_t)idx * 8) = *(int4*)o;
}

// ---------------------------------------------------------------- GEMM embed
__global__ __launch_bounds__(NTHR, 2) void gemm_embed_k(const float* __restrict__ bias) {
    __shared__ __align__(16) __nv_bfloat16 sA[2 * BM * BKP];
    __shared__ __align__(16) __nv_bfloat16 sB[2 * BN * BKP];
    uint32_t sAu = (uint32_t)__cvta_generic_to_shared(sA);
    uint32_t sBu = (uint32_t)__cvta_generic_to_shared(sB);
    const __nv_bfloat16* aG = g_Ah + (size_t)blockIdx.x * BM * KDIM;
    const __nv_bfloat16* bG = g_Wh + (size_t)blockIdx.y * BN * KDIM;
    float acc[4][4][4] = {};
    mainloop(aG, KDIM, bG, KDIM, KDIM / BKC, sAu, sBu, acc);

    int lane = threadIdx.x & 31, warp = threadIdx.x >> 5;
    int wm = (warp >> 2) * 64, wn = (warp & 3) * 32;
    int g = lane >> 2, lt = lane & 3;
    int rowB = blockIdx.x * BM + wm;
    int colB = blockIdx.y * BN + wn;
    #pragma unroll
    for (int mi = 0; mi < 4; mi++)
        #pragma unroll
        for (int nj = 0; nj < 4; nj++) {
            int col = colB + nj * 8 + lt * 2;
            float b0 = bias[col], b1 = bias[col + 1];
            int r0 = rowB + mi * 16 + g;
            float2 v0 = { acc[mi][nj][0] + b0, acc[mi][nj][1] + b1 };
            float2 v1 = { acc[mi][nj][2] + b0, acc[mi][nj][3] + b1 };
            *(float2*)(g_pn + (size_t)r0 * DH + col)       = v0;
            *(float2*)(g_pn + (size_t)(r0 + 8) * DH + col) = v1;
        }
}

// ---------------------------------------------------------------- L2 normalize
__global__ void norm_patch_k() {
    int gw = (blockIdx.x * blockDim.x + threadIdx.x) >> 5;
    int lane = threadIdx.x & 31;
    if (gw >= MTOT) return;
    const float4* r = (const float4*)(g_pn + (size_t)gw * DH);
    ushort4* dst = (ushort4*)(g_pnh + (size_t)gw * DH);
    float s = 0.f; float4 v[6];
    #pragma unroll
    for (int i = 0; i < 6; i++) {
        v[i] = r[lane + 32*i];
        s += v[i].x*v[i].x + v[i].y*v[i].y + v[i].z*v[i].z + v[i].w*v[i].w;
    }
    #pragma unroll
    for (int o = 16; o; o >>= 1) s += __shfl_xor_sync(0xffffffffu, s, o);
    float inv = 1.0f / fmaxf(sqrtf(s), EPSN);
    #pragma unroll
    for (int i = 0; i < 6; i++) {
        __nv_bfloat16 o4[4];
        o4[0] = __float2bfloat16_rn(v[i].x * inv);
        o4[1] = __float2bfloat16_rn(v[i].y * inv);
        o4[2] = __float2bfloat16_rn(v[i].z * inv);
        o4[3] = __float2bfloat16_rn(v[i].w * inv);
        dst[lane + 32*i] = *(ushort4*)o4;
    }
}

__global__ void norm_latent_k(const float* __restrict__ latent) {
    int gw = (blockIdx.x * blockDim.x + threadIdx.x) >> 5;
    int lane = threadIdx.x & 31;
    if (gw >= LLAT) return;
    const float4* src = (const float4*)(latent + (size_t)gw * DH);
    ushort4* dst = (ushort4*)(g_lnh + (size_t)gw * DH);
    float s = 0.f; float4 v[6];
    #pragma unroll
    for (int i = 0; i < 6; i++) {
        v[i] = src[lane + 32*i];
        s += v[i].x*v[i].x + v[i].y*v[i].y + v[i].z*v[i].z + v[i].w*v[i].w;
    }
    #pragma unroll
    for (int o = 16; o; o >>= 1) s += __shfl_xor_sync(0xffffffffu, s, o);
    float inv = 1.0f / fmaxf(sqrtf(s), EPSN);
    #pragma unroll
    for (int i = 0; i < 6; i++) {
        __nv_bfloat16 o4[4];
        o4[0] = __float2bfloat16_rn(v[i].x * inv);
        o4[1] = __float2bfloat16_rn(v[i].y * inv);
        o4[2] = __float2bfloat16_rn(v[i].z * inv);
        o4[3] = __float2bfloat16_rn(v[i].w * inv);
        dst[lane + 32*i] = *(ushort4*)o4;
    }
}

// ---------------------------------------------------------------- far
// per-batch 576x576, 128-tiles (5x5, masked), upper triangle * 2
__global__ __launch_bounds__(NTHR, 2) void far_k() {
    int tI = blockIdx.x, tJ = blockIdx.y, b = blockIdx.z;
    if (tJ < tI) return;
    __shared__ __align__(16) __nv_bfloat16 sA[2 * BM * BKP];
    __shared__ __align__(16) __nv_bfloat16 sB[2 * BN * BKP];
    __shared__ float red[NTHR];
    uint32_t sAu = (uint32_t)__cvta_generic_to_shared(sA);
    uint32_t sBu = (uint32_t)__cvta_generic_to_shared(sB);
    const __nv_bfloat16* aG = g_pnh + ((size_t)b * NPAT + tI * BM) * DH;
    const __nv_bfloat16* bG = g_pnh + ((size_t)b * NPAT + tJ * BM) * DH;
    float acc[4][4][4] = {};
    mainloop(aG, DH, bG, DH, DH / BKC, sAu, sBu, acc);

    int tid = threadIdx.x;
    int lane = tid & 31, warp = tid >> 5;
    int wm = (warp >> 2) * 64, wn = (warp & 3) * 32;
    int g = lane >> 2, lt = lane & 3;
    bool diag = (tI == tJ);
    float part = 0.f;
    #pragma unroll
    for (int mi = 0; mi < 4; mi++)
        #pragma unroll
        for (int nj = 0; nj < 4; nj++) {
            int gr0 = tI * BM + wm + mi * 16 + g;     // local row within batch
            int gc0 = tJ * BM + wn + nj * 8 + lt * 2; // local col within batch
            float e0 = __expf(acc[mi][nj][0] * TAU_INV);
            float e1 = __expf(acc[mi][nj][1] * TAU_INV);
            float e2 = __expf(acc[mi][nj][2] * TAU_INV);
            float e3 = __expf(acc[mi][nj][3] * TAU_INV);
            bool c0 = (gr0 < NPAT)     && (gc0 < NPAT);
            bool c1 = (gr0 < NPAT)     && (gc0 + 1 < NPAT);
            bool c2 = (gr0 + 8 < NPAT) && (gc0 < NPAT);
            bool c3 = (gr0 + 8 < NPAT) && (gc0 + 1 < NPAT);
            if (diag) {
                part += (c0 && gr0     != gc0    ) ? e0 : 0.f;
                part += (c1 && gr0     != gc0 + 1) ? e1 : 0.f;
                part += (c2 && gr0 + 8 != gc0    ) ? e2 : 0.f;
                part += (c3 && gr0 + 8 != gc0 + 1) ? e3 : 0.f;
            } else {
                part += c0 ? 2.f * e0 : 0.f;
                part += c1 ? 2.f * e1 : 0.f;
                part += c2 ? 2.f * e2 : 0.f;
                part += c3 ? 2.f * e3 : 0.f;
            }
        }
    red[tid] = part; __syncthreads();
    for (int s = NTHR / 2; s > 0; s >>= 1) {
        if (tid < s) red[tid] += red[tid + s];
        __syncthreads();
    }
    if (tid == 0) atomicAdd(&g_far[b], (double)red[0]);
}

// ---------------------------------------------------------------- close
// one big GEMM 36864 x 1024; batch split per row in epilogue
__global__ __launch_bounds__(NTHR, 2) void close_k() {
    __shared__ __align__(16) __nv_bfloat16 sA[2 * BM * BKP];
    __shared__ __align__(16) __nv_bfloat16 sB[2 * BN * BKP];
    __shared__ float red[NTHR];
    uint32_t sAu = (uint32_t)__cvta_generic_to_shared(sA);
    uint32_t sBu = (uint32_t)__cvta_generic_to_shared(sB);
    const __nv_bfloat16* aG = g_pnh + (size_t)blockIdx.x * BM * DH;
    const __nv_bfloat16* bG = g_lnh + (size_t)blockIdx.y * BN * DH;
    float acc[4][4][4] = {};
    mainloop(aG, DH, bG, DH, DH / BKC, sAu, sBu, acc);

    int tid = threadIdx.x;
    int lane = tid & 31, warp = tid >> 5;
    int wm = (warp >> 2) * 64;
    int g = lane >> 2;
    int r0t = blockIdx.x * BM;
    int b_lo = r0t / NPAT;
    int bound = (b_lo + 1) * NPAT;   // rows >= bound belong to b_lo+1
    float plo = 0.f, phi = 0.f;
    #pragma unroll
    for (int mi = 0; mi < 4; mi++) {
        int gr0 = r0t + wm + mi * 16 + g;
        #pragma unroll
        for (int nj = 0; nj < 4; nj++) {
            float e0 = __expf(acc[mi][nj][0] * TAU_INV);
            float e1 = __expf(acc[mi][nj][1] * TAU_INV);
            float e2 = __expf(acc[mi][nj][2] * TAU_INV);
            float e3 = __expf(acc[mi][nj][3] * TAU_INV);
            if (gr0 < bound)     plo += e0 + e1; else phi += e0 + e1;
            if (gr0 + 8 < bound) plo += e2 + e3; else phi += e2 + e3;
        }
    }
    red[tid] = plo; __syncthreads();
    for (int s = NTHR / 2; s > 0; s >>= 1) {
        if (tid < s) red[tid] += red[tid + s];
        __syncthreads();
    }
    if (tid == 0) atomicAdd(&g_close[b_lo], (double)red[0]);
    __syncthreads();
    red[tid] = phi; __syncthreads();
    for (int s = NTHR / 2; s > 0; s >>= 1) {
        if (tid < s) red[tid] += red[tid + s];
        __syncthreads();
    }
    if (tid == 0 && b_lo + 1 < BATCH) atomicAdd(&g_close[b_lo + 1], (double)red[0]);
}

// ---------------------------------------------------------------- finish
__global__ void finish_k(float* out) {
    __shared__ double sh[BATCH];
    int t = threadIdx.x;
    sh[t] = log(g_far[t]) - log(g_close[t]);
    __syncthreads();
    if (t == 0) {
        double s = 0.0;
        for (int i = 0; i < BATCH; i++) s += sh[i];
        out[0] = (float)(s / (double)BATCH);
    }
}

// ---------------------------------------------------------------- launch
extern "C" void kernel_launch(void* const* d_in, const int* in_sizes, int n_in,
                              void* d_out, int out_size) {
    const float* x      = (const float*)d_in[0];
    const float* conv_w = (const float*)d_in[1];
    const float* conv_b = (const float*)d_in[2];
    const float* latent = (const float*)d_in[3];
    float* out = (float*)d_out;

    init_k<<<1, 64>>>();
    im2col_k<<<(MTOT * (KDIM / 8)) / 256, 256>>>(x);
    wconv_k<<<(DH * KDIM / 8) / 256, 256>>>(conv_w);
    gemm_embed_k<<<dim3(MTOT / BM, DH / BN), NTHR>>>(conv_b);
    norm_patch_k<<<(MTOT * 32) / 256, 256>>>();
    norm_latent_k<<<(LLAT * 32) / 256, 256>>>(latent);
    far_k<<<dim3(5, 5, BATCH), NTHR>>>();
    close_k<<<dim3(MTOT / BM, LLAT / BN), NTHR>>>();
    finish_k<<<1, BATCH>>>(out);
}